// round 3
// baseline (speedup 1.0000x reference)
#include <cuda_runtime.h>
#include <cuda_bf16.h>

#define D_NODE 256
#define D_OUT  128
#define N_MAX  100000

// Scratch: ax = segment_sum(x[src], dst)  [N, 256]. float4-typed for
// alignment-safe vector access; kernels reference the symbol directly.
__device__ float4 g_ax4[N_MAX * D_NODE / 4];

// ---------------------------------------------------------------------------
// Zero the ax scratch (float4 grid-stride)
// ---------------------------------------------------------------------------
__global__ void zero_ax_kernel(int n4) {
    int i = blockIdx.x * blockDim.x + threadIdx.x;
    if (i < n4) g_ax4[i] = make_float4(0.f, 0.f, 0.f, 0.f);
}

// ---------------------------------------------------------------------------
// Scatter-add: one warp per edge. Each lane handles 8 contiguous floats
// (2 float4 gathers from x[src], 8 atomicAdds into ax[dst]).
// edge_index is int32 (JAX demotes int64 -> int32 by default).
// ---------------------------------------------------------------------------
__global__ void scatter_add_kernel(const float* __restrict__ x,
                                   const int* __restrict__ ei,
                                   int E) {
    int e = blockIdx.x * (blockDim.x >> 5) + (threadIdx.x >> 5);
    if (e >= E) return;
    int lane = threadIdx.x & 31;
    int s = ei[e];
    int d = ei[(size_t)E + e];
    const float4* xs = reinterpret_cast<const float4*>(x + (size_t)s * D_NODE);
    float* dst = reinterpret_cast<float*>(g_ax4) + (size_t)d * D_NODE;
#pragma unroll
    for (int i = 0; i < 2; i++) {
        float4 v = xs[lane + 32 * i];
        int base = (lane + 32 * i) * 4;
        atomicAdd(dst + base + 0, v.x);
        atomicAdd(dst + base + 1, v.y);
        atomicAdd(dst + base + 2, v.z);
        atomicAdd(dst + base + 3, v.w);
    }
}

// ---------------------------------------------------------------------------
// fp32 register-tiled SGEMM: C[M,128] = A[M,K] @ B[K,128]
// BM=64, BN=128, BK=16, 256 threads, per-thread tile 4 rows x 8 cols.
// If use_gax != 0, A is the g_ax4 device scratch (Ain ignored).
// ---------------------------------------------------------------------------
__global__ __launch_bounds__(256) void sgemm128_kernel(
    const float* __restrict__ Ain, const float* __restrict__ B,
    float* __restrict__ C, int M, int K, int use_gax) {
    const int BM = 64, BN = 128, BK = 16;
    __shared__ float As[BK][BM];
    __shared__ float Bs[BK][BN];

    const float* A = use_gax ? reinterpret_cast<const float*>(g_ax4) : Ain;

    int tid = threadIdx.x;
    int tx = tid & 15;   // column group (0..15)
    int ty = tid >> 4;   // row group (0..15)
    int m0 = blockIdx.x * BM;

    float acc[4][8];
#pragma unroll
    for (int i = 0; i < 4; i++)
#pragma unroll
        for (int j = 0; j < 8; j++) acc[i][j] = 0.f;

    for (int k0 = 0; k0 < K; k0 += BK) {
        // Load A tile 64x16: one float4 per thread, store transposed.
        {
            int row = tid >> 2;
            int kq = (tid & 3) * 4;
            float4 v = make_float4(0.f, 0.f, 0.f, 0.f);
            if (m0 + row < M)
                v = *reinterpret_cast<const float4*>(A + (size_t)(m0 + row) * K + k0 + kq);
            As[kq + 0][row] = v.x;
            As[kq + 1][row] = v.y;
            As[kq + 2][row] = v.z;
            As[kq + 3][row] = v.w;
        }
        // Load B tile 16x128: two float4 per thread.
#pragma unroll
        for (int i = 0; i < 2; i++) {
            int f = tid + i * 256;
            int row = f >> 5;
            int c4 = (f & 31) * 4;
            *reinterpret_cast<float4*>(&Bs[row][c4]) =
                *reinterpret_cast<const float4*>(B + (size_t)(k0 + row) * BN + c4);
        }
        __syncthreads();

#pragma unroll
        for (int kk = 0; kk < BK; kk++) {
            float a[4], b[8];
            float4 av = *reinterpret_cast<const float4*>(&As[kk][ty * 4]);
            a[0] = av.x; a[1] = av.y; a[2] = av.z; a[3] = av.w;
            float4 b0 = *reinterpret_cast<const float4*>(&Bs[kk][tx * 4]);
            float4 b1 = *reinterpret_cast<const float4*>(&Bs[kk][64 + tx * 4]);
            b[0] = b0.x; b[1] = b0.y; b[2] = b0.z; b[3] = b0.w;
            b[4] = b1.x; b[5] = b1.y; b[6] = b1.z; b[7] = b1.w;
#pragma unroll
            for (int i = 0; i < 4; i++)
#pragma unroll
                for (int j = 0; j < 8; j++) acc[i][j] = fmaf(a[i], b[j], acc[i][j]);
        }
        __syncthreads();
    }

    // Write back: two float4 stores per owned row.
#pragma unroll
    for (int i = 0; i < 4; i++) {
        int row = m0 + ty * 4 + i;
        if (row < M) {
            float4 v0 = make_float4(acc[i][0], acc[i][1], acc[i][2], acc[i][3]);
            float4 v1 = make_float4(acc[i][4], acc[i][5], acc[i][6], acc[i][7]);
            *reinterpret_cast<float4*>(C + (size_t)row * BN + tx * 4) = v0;
            *reinterpret_cast<float4*>(C + (size_t)row * BN + 64 + tx * 4) = v1;
        }
    }
}

// ---------------------------------------------------------------------------
// DistMult scores: one warp per edge.
// raw = sum_d axw[src,d] * ew[e,d] * axw[dst,d];  out = raw * tc[e] * lw[0]
// ---------------------------------------------------------------------------
__global__ void scores_kernel(const float* __restrict__ axw,
                              const float* __restrict__ ew,
                              const int* __restrict__ ei,
                              const float* __restrict__ tc,
                              const float* __restrict__ lw,
                              float* __restrict__ out, int E) {
    int e = blockIdx.x * (blockDim.x >> 5) + (threadIdx.x >> 5);
    if (e >= E) return;
    int lane = threadIdx.x & 31;
    int s = ei[e];
    int d = ei[(size_t)E + e];
    float4 h = *reinterpret_cast<const float4*>(axw + (size_t)s * D_OUT + lane * 4);
    float4 t = *reinterpret_cast<const float4*>(axw + (size_t)d * D_OUT + lane * 4);
    float4 w = *reinterpret_cast<const float4*>(ew + (size_t)e * D_OUT + lane * 4);
    float r = h.x * w.x * t.x + h.y * w.y * t.y + h.z * w.z * t.z + h.w * w.w * t.w;
#pragma unroll
    for (int o = 16; o > 0; o >>= 1) r += __shfl_xor_sync(0xFFFFFFFFu, r, o);
    if (lane == 0) out[e] = r * tc[e] * lw[0];
}

// ---------------------------------------------------------------------------
extern "C" void kernel_launch(void* const* d_in, const int* in_sizes, int n_in,
                              void* d_out, int out_size) {
    const float* x         = (const float*)d_in[0];   // [N, 256]
    const float* edge_attr = (const float*)d_in[1];   // [E, 128]
    const float* tc        = (const float*)d_in[2];   // [E]
    const float* Wn        = (const float*)d_in[3];   // [256, 128]
    const float* We        = (const float*)d_in[4];   // [128, 128]
    const float* lw        = (const float*)d_in[5];   // [1]
    const int*   ei        = (const int*)d_in[6];     // [2, E] int32

    int N = in_sizes[0] / D_NODE;
    int E = in_sizes[6] / 2;

    float* axw_out = (float*)d_out;                       // [N, 128]
    float* ew_out  = axw_out + (size_t)N * D_OUT;          // [E, 128]
    float* sc_out  = ew_out + (size_t)E * D_OUT;           // [E]

    // 1) zero ax scratch
    int n4 = N * D_NODE / 4;
    zero_ax_kernel<<<(n4 + 255) / 256, 256>>>(n4);

    // 2) scatter-add x[src] into ax[dst]
    scatter_add_kernel<<<(E + 7) / 8, 256>>>(x, ei, E);

    // 3) axw = ax @ Wn   (A comes from device scratch)
    sgemm128_kernel<<<(N + 63) / 64, 256>>>(nullptr, Wn, axw_out, N, D_NODE, 1);

    // 4) ew = edge_attr @ We
    sgemm128_kernel<<<(E + 63) / 64, 256>>>(edge_attr, We, ew_out, E, 128, 0);

    // 5) DistMult scores
    scores_kernel<<<(E + 7) / 8, 256>>>(axw_out, ew_out, ei, tc, lw, sc_out, E);
}

// round 4
// speedup vs baseline: 1.2980x; 1.2980x over previous
#include <cuda_runtime.h>
#include <cuda_bf16.h>

#define D_NODE 256
#define D_OUT  128
#define N_MAX  100000

// Scratch: ax = segment_sum(x[src], dst)  [N, 256].
__device__ float4 g_ax4[N_MAX * D_NODE / 4];

// ---------------------------------------------------------------------------
// Zero the ax scratch
// ---------------------------------------------------------------------------
__global__ void zero_ax_kernel(int n4) {
    int i = blockIdx.x * blockDim.x + threadIdx.x;
    if (i < n4) g_ax4[i] = make_float4(0.f, 0.f, 0.f, 0.f);
}

// ---------------------------------------------------------------------------
// Scatter-add: one warp per edge, vector reduction (red.global.add.v4.f32).
// Each lane handles 8 floats = 2 float4 gathers + 2 v4 reductions.
// ---------------------------------------------------------------------------
__device__ __forceinline__ void red_add_v4(float* p, float4 v) {
    asm volatile("red.global.add.v4.f32 [%0], {%1, %2, %3, %4};"
                 :: "l"(p), "f"(v.x), "f"(v.y), "f"(v.z), "f"(v.w)
                 : "memory");
}

__global__ void scatter_add_kernel(const float* __restrict__ x,
                                   const int* __restrict__ ei,
                                   int E) {
    int e = blockIdx.x * (blockDim.x >> 5) + (threadIdx.x >> 5);
    if (e >= E) return;
    int lane = threadIdx.x & 31;
    int s = ei[e];
    int d = ei[(size_t)E + e];
    const float4* xs = reinterpret_cast<const float4*>(x + (size_t)s * D_NODE);
    float* dst = reinterpret_cast<float*>(g_ax4) + (size_t)d * D_NODE;
#pragma unroll
    for (int i = 0; i < 2; i++) {
        float4 v = xs[lane + 32 * i];
        red_add_v4(dst + (lane + 32 * i) * 4, v);
    }
}

// ---------------------------------------------------------------------------
// fp32 register-tiled SGEMM: C[M,128] = A[M,K] @ B[K,128]
// BM=128, BN=128, BK=16, 256 threads, per-thread tile 8 rows x 8 cols.
// Halved LDS-per-FMA vs the 4x8 tile (L1 was the bottleneck at 89.6%).
// If use_gax != 0, A is the g_ax4 device scratch.
// ---------------------------------------------------------------------------
__global__ __launch_bounds__(256) void sgemm128_kernel(
    const float* __restrict__ Ain, const float* __restrict__ B,
    float* __restrict__ C, int M, int K, int use_gax) {
    const int BM = 128, BN = 128, BK = 16;
    __shared__ float As[BK][BM];
    __shared__ float Bs[BK][BN];

    const float* A = use_gax ? reinterpret_cast<const float*>(g_ax4) : Ain;

    int tid = threadIdx.x;
    int tx = tid & 15;   // column group (0..15): cols tx*4..+3 and 64+tx*4..+3
    int ty = tid >> 4;   // row group (0..15): rows ty*8..ty*8+7
    int m0 = blockIdx.x * BM;

    float acc[8][8];
#pragma unroll
    for (int i = 0; i < 8; i++)
#pragma unroll
        for (int j = 0; j < 8; j++) acc[i][j] = 0.f;

    for (int k0 = 0; k0 < K; k0 += BK) {
        // Load A tile 128x16: two float4 per thread, store transposed.
#pragma unroll
        for (int i = 0; i < 2; i++) {
            int f = tid + i * 256;
            int row = f >> 2;            // 0..127
            int kq = (f & 3) * 4;        // 0,4,8,12
            float4 v = make_float4(0.f, 0.f, 0.f, 0.f);
            if (m0 + row < M)
                v = *reinterpret_cast<const float4*>(A + (size_t)(m0 + row) * K + k0 + kq);
            As[kq + 0][row] = v.x;
            As[kq + 1][row] = v.y;
            As[kq + 2][row] = v.z;
            As[kq + 3][row] = v.w;
        }
        // Load B tile 16x128: two float4 per thread.
#pragma unroll
        for (int i = 0; i < 2; i++) {
            int f = tid + i * 256;
            int row = f >> 5;            // 0..15
            int c4 = (f & 31) * 4;       // 0..124
            *reinterpret_cast<float4*>(&Bs[row][c4]) =
                *reinterpret_cast<const float4*>(B + (size_t)(k0 + row) * BN + c4);
        }
        __syncthreads();

#pragma unroll
        for (int kk = 0; kk < BK; kk++) {
            float a[8], b[8];
            float4 a0 = *reinterpret_cast<const float4*>(&As[kk][ty * 8]);
            float4 a1 = *reinterpret_cast<const float4*>(&As[kk][ty * 8 + 4]);
            a[0] = a0.x; a[1] = a0.y; a[2] = a0.z; a[3] = a0.w;
            a[4] = a1.x; a[5] = a1.y; a[6] = a1.z; a[7] = a1.w;
            float4 b0 = *reinterpret_cast<const float4*>(&Bs[kk][tx * 4]);
            float4 b1 = *reinterpret_cast<const float4*>(&Bs[kk][64 + tx * 4]);
            b[0] = b0.x; b[1] = b0.y; b[2] = b0.z; b[3] = b0.w;
            b[4] = b1.x; b[5] = b1.y; b[6] = b1.z; b[7] = b1.w;
#pragma unroll
            for (int i = 0; i < 8; i++)
#pragma unroll
                for (int j = 0; j < 8; j++) acc[i][j] = fmaf(a[i], b[j], acc[i][j]);
        }
        __syncthreads();
    }

    // Write back: 8 rows x two float4 stores.
#pragma unroll
    for (int i = 0; i < 8; i++) {
        int row = m0 + ty * 8 + i;
        if (row < M) {
            float4 v0 = make_float4(acc[i][0], acc[i][1], acc[i][2], acc[i][3]);
            float4 v1 = make_float4(acc[i][4], acc[i][5], acc[i][6], acc[i][7]);
            *reinterpret_cast<float4*>(C + (size_t)row * BN + tx * 4) = v0;
            *reinterpret_cast<float4*>(C + (size_t)row * BN + 64 + tx * 4) = v1;
        }
    }
}

// ---------------------------------------------------------------------------
// DistMult scores: one warp per edge.
// ---------------------------------------------------------------------------
__global__ void scores_kernel(const float* __restrict__ axw,
                              const float* __restrict__ ew,
                              const int* __restrict__ ei,
                              const float* __restrict__ tc,
                              const float* __restrict__ lw,
                              float* __restrict__ out, int E) {
    int e = blockIdx.x * (blockDim.x >> 5) + (threadIdx.x >> 5);
    if (e >= E) return;
    int lane = threadIdx.x & 31;
    int s = ei[e];
    int d = ei[(size_t)E + e];
    float4 h = *reinterpret_cast<const float4*>(axw + (size_t)s * D_OUT + lane * 4);
    float4 t = *reinterpret_cast<const float4*>(axw + (size_t)d * D_OUT + lane * 4);
    float4 w = *reinterpret_cast<const float4*>(ew + (size_t)e * D_OUT + lane * 4);
    float r = h.x * w.x * t.x + h.y * w.y * t.y + h.z * w.z * t.z + h.w * w.w * t.w;
#pragma unroll
    for (int o = 16; o > 0; o >>= 1) r += __shfl_xor_sync(0xFFFFFFFFu, r, o);
    if (lane == 0) out[e] = r * tc[e] * lw[0];
}

// ---------------------------------------------------------------------------
extern "C" void kernel_launch(void* const* d_in, const int* in_sizes, int n_in,
                              void* d_out, int out_size) {
    const float* x         = (const float*)d_in[0];   // [N, 256]
    const float* edge_attr = (const float*)d_in[1];   // [E, 128]
    const float* tc        = (const float*)d_in[2];   // [E]
    const float* Wn        = (const float*)d_in[3];   // [256, 128]
    const float* We        = (const float*)d_in[4];   // [128, 128]
    const float* lw        = (const float*)d_in[5];   // [1]
    const int*   ei        = (const int*)d_in[6];     // [2, E] int32

    int N = in_sizes[0] / D_NODE;
    int E = in_sizes[6] / 2;

    float* axw_out = (float*)d_out;                       // [N, 128]
    float* ew_out  = axw_out + (size_t)N * D_OUT;          // [E, 128]
    float* sc_out  = ew_out + (size_t)E * D_OUT;           // [E]

    // 1) zero ax scratch
    int n4 = N * D_NODE / 4;
    zero_ax_kernel<<<(n4 + 255) / 256, 256>>>(n4);

    // 2) scatter-add x[src] into ax[dst]  (vector reductions)
    scatter_add_kernel<<<(E + 7) / 8, 256>>>(x, ei, E);

    // 3) axw = ax @ Wn
    sgemm128_kernel<<<(N + 127) / 128, 256>>>(nullptr, Wn, axw_out, N, D_NODE, 1);

    // 4) ew = edge_attr @ We
    sgemm128_kernel<<<(E + 127) / 128, 256>>>(edge_attr, We, ew_out, E, 128, 0);

    // 5) DistMult scores
    scores_kernel<<<(E + 7) / 8, 256>>>(axw_out, ew_out, ei, tc, lw, sc_out, E);
}